// round 11
// baseline (speedup 1.0000x reference)
#include <cuda_runtime.h>
#include <cuda_bf16.h>
#include <cstdint>

#define B_SZ  512
#define NIN   1024
#define NMID  8192
#define NOUT  1000
#define MPAD  1024
#define FAN   64
#define NCOND 2

// warp-MMA GEMM tiling (A fp32-staged + split at STS; B pre-split bf16)
#define TBM 128
#define TBN 128
#define TBK 16            // real-K elems per chunk
#define ROWB 48           // bf16 tile row stride bytes (32B data + 16B pad; conflict-free)
#define GEMM_THREADS 256

// ---------------------------------------------------------------------------
// Scratch (static device globals; referenced ONLY inside device code --
// passing them as kernel args from host binds the host shadow, which on
// GB300/ATS silently reads zeros / writes host RAM: the R5/R6 bug)
// ---------------------------------------------------------------------------
__device__ float4 g_act0v[(size_t)NMID * B_SZ / 4];           // fp32 [o][b]
__device__ float4 g_act1v[(size_t)NMID * B_SZ / 4];           // fp32 [o][b]
__device__ float4 g_wf4[NCOND][(size_t)(FAN / 4) * NMID];     // cond w packed
__device__ uint4  g_if4[(size_t)(FAN / 8) * NMID];            // cond idx packed u16
__device__ __nv_bfloat16 g_xh[(size_t)B_SZ * NIN];            // x hi  [b][k]
__device__ __nv_bfloat16 g_xl[(size_t)B_SZ * NIN];            // x lo
__device__ __nv_bfloat16 g_a1h[(size_t)B_SZ * NMID];          // act1 hi [b][o]
__device__ __nv_bfloat16 g_a1l[(size_t)B_SZ * NMID];          // act1 lo

// ---------------------------------------------------------------------------
__device__ __forceinline__ void mma16816(float* d,
                                         uint32_t a0, uint32_t a1, uint32_t a2, uint32_t a3,
                                         uint32_t b0, uint32_t b1) {
    asm volatile(
        "mma.sync.aligned.m16n8k16.row.col.f32.bf16.bf16.f32 "
        "{%0,%1,%2,%3}, {%4,%5,%6,%7}, {%8,%9}, {%0,%1,%2,%3};"
        : "+f"(d[0]), "+f"(d[1]), "+f"(d[2]), "+f"(d[3])
        : "r"(a0), "r"(a1), "r"(a2), "r"(a3), "r"(b0), "r"(b1));
}

__device__ __forceinline__ void split_bf16(float v, __nv_bfloat16& h, __nv_bfloat16& l) {
    h = __float2bfloat16(v);
    l = __float2bfloat16(v - __bfloat162float(h));
}
__device__ __forceinline__ void split4(float4 v, ushort4& hv, ushort4& lv) {
    __nv_bfloat16 h0, h1, h2, h3, l0, l1, l2, l3;
    split_bf16(v.x, h0, l0); split_bf16(v.y, h1, l1);
    split_bf16(v.z, h2, l2); split_bf16(v.w, h3, l3);
    hv = make_ushort4(__bfloat16_as_ushort(h0), __bfloat16_as_ushort(h1),
                      __bfloat16_as_ushort(h2), __bfloat16_as_ushort(h3));
    lv = make_ushort4(__bfloat16_as_ushort(l0), __bfloat16_as_ushort(l1),
                      __bfloat16_as_ushort(l2), __bfloat16_as_ushort(l3));
}

// ---------------------------------------------------------------------------
// prep kernels
// ---------------------------------------------------------------------------
__global__ void prep_x_kernel(const float* __restrict__ x) {
    int t = blockIdx.x * blockDim.x + threadIdx.x;       // over B_SZ*NIN/4
    if (t * 4 >= B_SZ * NIN) return;
    float4 v = __ldg((const float4*)(x) + t);
    ushort4 hv, lv;
    split4(v, hv, lv);
    ((ushort4*)g_xh)[t] = hv;
    ((ushort4*)g_xl)[t] = lv;
}
__global__ void prep_w_kernel(const float* __restrict__ Wmid) {
    int t = blockIdx.x * blockDim.x + threadIdx.x;
    if (t >= NCOND * (FAN / 4) * NMID) return;
    int phase = t / ((FAN / 4) * NMID);
    int rem = t - phase * (FAN / 4) * NMID;
    int g = rem / NMID, o = rem - g * NMID;
    const float* src = Wmid + (size_t)(phase * NMID + o) * FAN + g * 4;
    g_wf4[phase][(size_t)g * NMID + o] = make_float4(src[0], src[1], src[2], src[3]);
}
__global__ void prep_i_kernel(const int* __restrict__ idx) {
    int t = blockIdx.x * blockDim.x + threadIdx.x;
    if (t >= (FAN / 8) * NMID) return;
    int g = t / NMID, o = t - g * NMID;
    const int* src = idx + (size_t)o * FAN + g * 8;
    uint4 v;
    v.x = (unsigned)(src[0] & (NMID - 1)) | ((unsigned)(src[1] & (NMID - 1)) << 16);
    v.y = (unsigned)(src[2] & (NMID - 1)) | ((unsigned)(src[3] & (NMID - 1)) << 16);
    v.z = (unsigned)(src[4] & (NMID - 1)) | ((unsigned)(src[5] & (NMID - 1)) << 16);
    v.w = (unsigned)(src[6] & (NMID - 1)) | ((unsigned)(src[7] & (NMID - 1)) << 16);
    g_if4[(size_t)g * NMID + o] = v;
}

// ---------------------------------------------------------------------------
// warp-MMA bf16-split GEMM: D[m][n] = sum_k A[m][k]*B[n][k] = Ah*Bh + Ah*Bl + Al*Bh
// A fp32 (arg), split at STS. B pre-split bf16 (globals), straight LDG->STS.
// MODE 0: A=Win, B=g_xh/g_xl,   Ks=NIN,  out: g_act0[m*B_SZ+n]=relu(D+bias[m])
// MODE 1: A=Wout, B=g_a1h/g_a1l, Ks=NMID, out: atomicAdd(out[n*NOUT+m], D); A rows >= NOUT -> 0
// ---------------------------------------------------------------------------
template <int MODE>
__global__ __launch_bounds__(GEMM_THREADS) void mma_gemm(
    const float* __restrict__ Asrc,
    const float* __restrict__ bias, float* __restrict__ outp, int kIters)
{
    const float* __restrict__ A = Asrc;
    const __nv_bfloat16* __restrict__ Bh = (MODE == 0) ? g_xh : g_a1h;
    const __nv_bfloat16* __restrict__ Bl = (MODE == 0) ? g_xl : g_a1l;
    float* out = (MODE == 0) ? (float*)g_act0v : outp;
    const int Ks = (MODE == 0) ? NIN : NMID;

    __shared__ __align__(16) char smAh[TBM * ROWB];
    __shared__ __align__(16) char smAl[TBM * ROWB];
    __shared__ __align__(16) char smBh[TBN * ROWB];
    __shared__ __align__(16) char smBl[TBN * ROWB];

    int tid = threadIdx.x;
    int wid = tid >> 5, lid = tid & 31;
    int g = lid >> 2, t = lid & 3;
    int wm = (wid >> 1) * 32;               // warp M offset in tile
    int wn = (wid & 1) * 64;                // warp N offset in tile
    int m0 = blockIdx.y * TBM;
    int n0 = blockIdx.x * TBN;
    int kk0 = blockIdx.z * kIters * TBK;

    // A staging: 512 chunks of 16B (4 fp32); 2 per thread
    int ra0 = tid >> 2,          sa0 = (tid & 3) * 4;            // seg in floats
    int ra1 = (tid + 256) >> 2,  sa1 = ((tid + 256) & 3) * 4;
    // B staging (bf16): 256 chunks of 16B (8 bf16) per array; 1 per thread
    int rb = tid >> 1,           sb = (tid & 1) * 8;             // seg in elems

    float4 fA0, fA1;
    uint4 rBh, rBl;
    float acc[2][8][4] = {};

#define LDG_CHUNKS(it)                                                             \
    do {                                                                           \
        int kk = kk0 + (it) * TBK;                                                 \
        fA0 = (MODE == 1 && m0 + ra0 >= NOUT) ? make_float4(0.f, 0.f, 0.f, 0.f)    \
              : __ldg((const float4*)(A + (size_t)(m0 + ra0) * Ks + kk + sa0));    \
        fA1 = (MODE == 1 && m0 + ra1 >= NOUT) ? make_float4(0.f, 0.f, 0.f, 0.f)    \
              : __ldg((const float4*)(A + (size_t)(m0 + ra1) * Ks + kk + sa1));    \
        rBh = __ldg((const uint4*)(Bh + (size_t)(n0 + rb) * Ks + kk + sb));        \
        rBl = __ldg((const uint4*)(Bl + (size_t)(n0 + rb) * Ks + kk + sb));        \
    } while (0)

#define CVT_STS()                                                                  \
    do {                                                                           \
        ushort4 hv, lv;                                                            \
        split4(fA0, hv, lv);                                                       \
        *(ushort4*)(smAh + ra0 * ROWB + sa0 * 2) = hv;                             \
        *(ushort4*)(smAl + ra0 * ROWB + sa0 * 2) = lv;                             \
        split4(fA1, hv, lv);                                                       \
        *(ushort4*)(smAh + ra1 * ROWB + sa1 * 2) = hv;                             \
        *(ushort4*)(smAl + ra1 * ROWB + sa1 * 2) = lv;                             \
        *(uint4*)(smBh + rb * ROWB + sb * 2) = rBh;                                \
        *(uint4*)(smBl + rb * ROWB + sb * 2) = rBl;                                \
    } while (0)

    LDG_CHUNKS(0);

    int koff = 4 * t;                       // byte offset in 32B bf16 row
    for (int it = 0; it < kIters; it++) {
        __syncthreads();                    // previous compute done everywhere
        CVT_STS();
        __syncthreads();
        if (it + 1 < kIters) LDG_CHUNKS(it + 1);   // hidden under compute below

        uint32_t a[2][4];
        // ---- aH fragments (reused for Bh and Bl passes) ----
#pragma unroll
        for (int mi = 0; mi < 2; mi++) {
            const char* base = smAh + (wm + mi * 16 + g) * ROWB + koff;
            a[mi][0] = *(const uint32_t*)(base);
            a[mi][1] = *(const uint32_t*)(base + 8 * ROWB);
            a[mi][2] = *(const uint32_t*)(base + 16);
            a[mi][3] = *(const uint32_t*)(base + 8 * ROWB + 16);
        }
        // pass 0: aH x bH
#pragma unroll
        for (int nj = 0; nj < 4; nj++) {
            const char* bb = smBh + (wn + nj * 16 + g) * ROWB + koff;
            uint32_t b0 = *(const uint32_t*)(bb);
            uint32_t b1 = *(const uint32_t*)(bb + 16);
            uint32_t b2 = *(const uint32_t*)(bb + 8 * ROWB);
            uint32_t b3 = *(const uint32_t*)(bb + 8 * ROWB + 16);
#pragma unroll
            for (int mi = 0; mi < 2; mi++) {
                mma16816(acc[mi][nj * 2],     a[mi][0], a[mi][1], a[mi][2], a[mi][3], b0, b1);
                mma16816(acc[mi][nj * 2 + 1], a[mi][0], a[mi][1], a[mi][2], a[mi][3], b2, b3);
            }
        }
        // pass 1: aH x bL
#pragma unroll
        for (int nj = 0; nj < 4; nj++) {
            const char* bb = smBl + (wn + nj * 16 + g) * ROWB + koff;
            uint32_t b0 = *(const uint32_t*)(bb);
            uint32_t b1 = *(const uint32_t*)(bb + 16);
            uint32_t b2 = *(const uint32_t*)(bb + 8 * ROWB);
            uint32_t b3 = *(const uint32_t*)(bb + 8 * ROWB + 16);
#pragma unroll
            for (int mi = 0; mi < 2; mi++) {
                mma16816(acc[mi][nj * 2],     a[mi][0], a[mi][1], a[mi][2], a[mi][3], b0, b1);
                mma16816(acc[mi][nj * 2 + 1], a[mi][0], a[mi][1], a[mi][2], a[mi][3], b2, b3);
            }
        }
        // ---- aL fragments ----
#pragma unroll
        for (int mi = 0; mi < 2; mi++) {
            const char* base = smAl + (wm + mi * 16 + g) * ROWB + koff;
            a[mi][0] = *(const uint32_t*)(base);
            a[mi][1] = *(const uint32_t*)(base + 8 * ROWB);
            a[mi][2] = *(const uint32_t*)(base + 16);
            a[mi][3] = *(const uint32_t*)(base + 8 * ROWB + 16);
        }
        // pass 2: aL x bH
#pragma unroll
        for (int nj = 0; nj < 4; nj++) {
            const char* bb = smBh + (wn + nj * 16 + g) * ROWB + koff;
            uint32_t b0 = *(const uint32_t*)(bb);
            uint32_t b1 = *(const uint32_t*)(bb + 16);
            uint32_t b2 = *(const uint32_t*)(bb + 8 * ROWB);
            uint32_t b3 = *(const uint32_t*)(bb + 8 * ROWB + 16);
#pragma unroll
            for (int mi = 0; mi < 2; mi++) {
                mma16816(acc[mi][nj * 2],     a[mi][0], a[mi][1], a[mi][2], a[mi][3], b0, b1);
                mma16816(acc[mi][nj * 2 + 1], a[mi][0], a[mi][1], a[mi][2], a[mi][3], b2, b3);
            }
        }
    }
#undef LDG_CHUNKS
#undef CVT_STS

    // epilogue: c0,c1 at (m, n=2t), c2,c3 at (m+8, n=2t)
    int mrow = g;
    int ncol = t * 2;
#pragma unroll
    for (int mi = 0; mi < 2; mi++) {
        int m = m0 + wm + mi * 16 + mrow;
        if (MODE == 0) {
            float bv0 = bias[m], bv8 = bias[m + 8];
#pragma unroll
            for (int n8 = 0; n8 < 8; n8++) {
                int n = n0 + wn + n8 * 8 + ncol;
                float* c = acc[mi][n8];
                float2 lo = make_float2(fmaxf(c[0] + bv0, 0.f), fmaxf(c[1] + bv0, 0.f));
                float2 hi = make_float2(fmaxf(c[2] + bv8, 0.f), fmaxf(c[3] + bv8, 0.f));
                *(float2*)(out + (size_t)m * B_SZ + n) = lo;
                *(float2*)(out + (size_t)(m + 8) * B_SZ + n) = hi;
            }
        } else {
#pragma unroll
            for (int n8 = 0; n8 < 8; n8++) {
                int n = n0 + wn + n8 * 8 + ncol;
                float* c = acc[mi][n8];
                if (m < NOUT) {
                    atomicAdd(out + (size_t)n * NOUT + m, c[0]);
                    atomicAdd(out + (size_t)(n + 1) * NOUT + m, c[1]);
                }
                if (m + 8 < NOUT) {
                    atomicAdd(out + (size_t)n * NOUT + m + 8, c[2]);
                    atomicAdd(out + (size_t)(n + 1) * NOUT + m + 8, c[3]);
                }
            }
        }
    }
}

// ---------------------------------------------------------------------------
// Condensed layer, 2-o interleaved for ILP (two independent load/FMA chains).
// phase 0: fp32 [o][b] -> fp32 [o][b]
// phase 1: fp32 [o][b] -> bf16 hi/lo [b][o] (g_a1h/g_a1l)
// ---------------------------------------------------------------------------
__global__ __launch_bounds__(1024) void cond_kernel(int phase, const float* __restrict__ bias) {
    extern __shared__ float4 hs[];   // [NMID]
    const float4* hin = (phase == 0) ? g_act0v : g_act1v;
    const float4* wp = g_wf4[phase];
    int bq = blockIdx.x;
    int b0 = bq * 4;
    int tid = threadIdx.x;

    for (int j = tid; j < NMID; j += 1024)
        hs[j] = hin[(size_t)j * (B_SZ / 4) + bq];
    __syncthreads();

#pragma unroll
    for (int oi = 0; oi < NMID / 1024; oi += 2) {
        int oA = oi * 1024 + tid;
        int oB = oA + 1024;
        float aAx = 0.f, aAy = 0.f, aAz = 0.f, aAw = 0.f;
        float aBx = 0.f, aBy = 0.f, aBz = 0.f, aBw = 0.f;
#pragma unroll
        for (int gg = 0; gg < FAN / 8; gg++) {
            uint4  ivA = g_if4[(size_t)gg * NMID + oA];
            uint4  ivB = g_if4[(size_t)gg * NMID + oB];
            float4 wA0 = wp[(size_t)(2 * gg) * NMID + oA];
            float4 wA1 = wp[(size_t)(2 * gg + 1) * NMID + oA];
            float4 wB0 = wp[(size_t)(2 * gg) * NMID + oB];
            float4 wB1 = wp[(size_t)(2 * gg + 1) * NMID + oB];
            {
                float4 h0 = hs[ivA.x & 0xffff];
                float4 h1 = hs[ivA.x >> 16];
                float4 h2 = hs[ivA.y & 0xffff];
                float4 h3 = hs[ivA.y >> 16];
                aAx = fmaf(wA0.x, h0.x, aAx); aAy = fmaf(wA0.x, h0.y, aAy);
                aAz = fmaf(wA0.x, h0.z, aAz); aAw = fmaf(wA0.x, h0.w, aAw);
                aAx = fmaf(wA0.y, h1.x, aAx); aAy = fmaf(wA0.y, h1.y, aAy);
                aAz = fmaf(wA0.y, h1.z, aAz); aAw = fmaf(wA0.y, h1.w, aAw);
                aAx = fmaf(wA0.z, h2.x, aAx); aAy = fmaf(wA0.z, h2.y, aAy);
                aAz = fmaf(wA0.z, h2.z, aAz); aAw = fmaf(wA0.z, h2.w, aAw);
                aAx = fmaf(wA0.w, h3.x, aAx); aAy = fmaf(wA0.w, h3.y, aAy);
                aAz = fmaf(wA0.w, h3.z, aAz); aAw = fmaf(wA0.w, h3.w, aAw);
                float4 h4 = hs[ivA.z & 0xffff];
                float4 h5 = hs[ivA.z >> 16];
                float4 h6 = hs[ivA.w & 0xffff];
                float4 h7 = hs[ivA.w >> 16];
                aAx = fmaf(wA1.x, h4.x, aAx); aAy = fmaf(wA1.x, h4.y, aAy);
                aAz = fmaf(wA1.x, h4.z, aAz); aAw = fmaf(wA1.x, h4.w, aAw);
                aAx = fmaf(wA1.y, h5.x, aAx); aAy = fmaf(wA1.y, h5.y, aAy);
                aAz = fmaf(wA1.y, h5.z, aAz); aAw = fmaf(wA1.y, h5.w, aAw);
                aAx = fmaf(wA1.z, h6.x, aAx); aAy = fmaf(wA1.z, h6.y, aAy);
                aAz = fmaf(wA1.z, h6.z, aAz); aAw = fmaf(wA1.z, h6.w, aAw);
                aAx = fmaf(wA1.w, h7.x, aAx); aAy = fmaf(wA1.w, h7.y, aAy);
                aAz = fmaf(wA1.w, h7.z, aAz); aAw = fmaf(wA1.w, h7.w, aAw);
            }
            {
                float4 h0 = hs[ivB.x & 0xffff];
                float4 h1 = hs[ivB.x >> 16];
                float4 h2 = hs[ivB.y & 0xffff];
                float4 h3 = hs[ivB.y >> 16];
                aBx = fmaf(wB0.x, h0.x, aBx); aBy = fmaf(wB0.x, h0.y, aBy);
                aBz = fmaf(wB0.x, h0.z, aBz); aBw = fmaf(wB0.x, h0.w, aBw);
                aBx = fmaf(wB0.y, h1.x, aBx); aBy = fmaf(wB0.y, h1.y, aBy);
                aBz = fmaf(wB0.y, h1.z, aBz); aBw = fmaf(wB0.y, h1.w, aBw);
                aBx = fmaf(wB0.z, h2.x, aBx); aBy = fmaf(wB0.z, h2.y, aBy);
                aBz = fmaf(wB0.z, h2.z, aBz); aBw = fmaf(wB0.z, h2.w, aBw);
                aBx = fmaf(wB0.w, h3.x, aBx); aBy = fmaf(wB0.w, h3.y, aBy);
                aBz = fmaf(wB0.w, h3.z, aBz); aBw = fmaf(wB0.w, h3.w, aBw);
                float4 h4 = hs[ivB.z & 0xffff];
                float4 h5 = hs[ivB.z >> 16];
                float4 h6 = hs[ivB.w & 0xffff];
                float4 h7 = hs[ivB.w >> 16];
                aBx = fmaf(wB1.x, h4.x, aBx); aBy = fmaf(wB1.x, h4.y, aBy);
                aBz = fmaf(wB1.x, h4.z, aBz); aBw = fmaf(wB1.x, h4.w, aBw);
                aBx = fmaf(wB1.y, h5.x, aBx); aBy = fmaf(wB1.y, h5.y, aBy);
                aBz = fmaf(wB1.y, h5.z, aBz); aBw = fmaf(wB1.y, h5.w, aBw);
                aBx = fmaf(wB1.z, h6.x, aBx); aBy = fmaf(wB1.z, h6.y, aBy);
                aBz = fmaf(wB1.z, h6.z, aBz); aBw = fmaf(wB1.z, h6.w, aBw);
                aBx = fmaf(wB1.w, h7.x, aBx); aBy = fmaf(wB1.w, h7.y, aBy);
                aBz = fmaf(wB1.w, h7.z, aBz); aBw = fmaf(wB1.w, h7.w, aBw);
            }
        }
        float bvA = bias[oA], bvB = bias[oB];
        float4 rA, rB;
        rA.x = fmaxf(aAx + bvA, 0.f); rA.y = fmaxf(aAy + bvA, 0.f);
        rA.z = fmaxf(aAz + bvA, 0.f); rA.w = fmaxf(aAw + bvA, 0.f);
        rB.x = fmaxf(aBx + bvB, 0.f); rB.y = fmaxf(aBy + bvB, 0.f);
        rB.z = fmaxf(aBz + bvB, 0.f); rB.w = fmaxf(aBw + bvB, 0.f);
        if (phase == 0) {
            g_act1v[(size_t)oA * (B_SZ / 4) + bq] = rA;
            g_act1v[(size_t)oB * (B_SZ / 4) + bq] = rB;
        } else {
            float vA[4] = {rA.x, rA.y, rA.z, rA.w};
            float vB[4] = {rB.x, rB.y, rB.z, rB.w};
#pragma unroll
            for (int i = 0; i < 4; i++) {
                __nv_bfloat16 h, l;
                split_bf16(vA[i], h, l);
                g_a1h[(size_t)(b0 + i) * NMID + oA] = h;
                g_a1l[(size_t)(b0 + i) * NMID + oA] = l;
                split_bf16(vB[i], h, l);
                g_a1h[(size_t)(b0 + i) * NMID + oB] = h;
                g_a1l[(size_t)(b0 + i) * NMID + oB] = l;
            }
        }
    }
}

// ---------------------------------------------------------------------------
__global__ void init_out_kernel(const float* __restrict__ bout, float* __restrict__ out) {
    int t = blockIdx.x * blockDim.x + threadIdx.x;
    if (t < B_SZ * NOUT) out[t] = bout[t % NOUT];
}

// ---------------------------------------------------------------------------
extern "C" void kernel_launch(void* const* d_in, const int* in_sizes, int n_in,
                              void* d_out, int out_size) {
    const float* x    = (const float*)d_in[0];
    const float* Win  = (const float*)d_in[1];
    const float* bin  = (const float*)d_in[2];
    const float* Wmid = (const float*)d_in[3];
    const float* bmid = (const float*)d_in[4];
    const float* Wout = (const float*)d_in[5];
    const float* bout = (const float*)d_in[6];
    const int*   idx  = (const int*)d_in[7];    // int32 (JAX x64 disabled)
    float* out = (float*)d_out;

    cudaFuncSetAttribute(cond_kernel, cudaFuncAttributeMaxDynamicSharedMemorySize, 131072);

    // prep (scratch globals bound inside device code)
    prep_x_kernel<<<(B_SZ * NIN / 4 + 255) / 256, 256>>>(x);
    prep_w_kernel<<<(NCOND * (FAN / 4) * NMID + 255) / 256, 256>>>(Wmid);
    prep_i_kernel<<<((FAN / 8) * NMID + 255) / 256, 256>>>(idx);

    // GEMM1: relu(W_in x^T + b_in) -> g_act0 fp32 [o][b]
    mma_gemm<0><<<dim3(B_SZ / TBN, NMID / TBM, 1), GEMM_THREADS>>>(
        Win, bin, nullptr, NIN / TBK);

    // condensed layers
    cond_kernel<<<B_SZ / 4, 1024, 131072>>>(0, bmid);
    cond_kernel<<<B_SZ / 4, 1024, 131072>>>(1, bmid + NMID);

    // GEMM3: out[b][m] = act1 . W_out^T + b_out  (split-K=8, atomic)
    init_out_kernel<<<(B_SZ * NOUT + 255) / 256, 256>>>(bout, out);
    mma_gemm<1><<<dim3(B_SZ / TBN, MPAD / TBM, 8), GEMM_THREADS>>>(
        Wout, nullptr, out, NMID / (TBK * 8));
}

// round 12
// speedup vs baseline: 1.0139x; 1.0139x over previous
#include <cuda_runtime.h>
#include <cuda_bf16.h>
#include <cstdint>

#define B_SZ  512
#define NIN   1024
#define NMID  8192
#define NOUT  1000
#define MPAD  1024
#define FAN   64
#define NCOND 2

// warp-MMA GEMM tiling (fp32 staged, hi/lo bf16 split at STS)
#define TBM 128
#define TBN 128
#define TBK 32            // real-K elems per chunk (2 k-steps of 16)
#define ROWB 80           // bf16 tile row stride bytes (64B data + 16B pad; word=20*row+t covers all banks)
#define GEMM_THREADS 256

// ---------------------------------------------------------------------------
// Scratch (static device globals; referenced ONLY inside device code --
// passing them as kernel args from host binds the host shadow, which on
// GB300/ATS silently reads zeros / writes host RAM: the R5/R6 bug)
// ---------------------------------------------------------------------------
__device__ float4 g_act0v[(size_t)NMID * B_SZ / 4];           // fp32 [o][b]
__device__ float4 g_act1v[(size_t)NMID * B_SZ / 4];           // fp32 [o][b]
__device__ float  g_a1t[(size_t)B_SZ * NMID];                 // fp32 [b][o] (cond1 out, GEMM3 B)
__device__ float4 g_wf4[NCOND][(size_t)(FAN / 4) * NMID];     // cond w packed
__device__ uint4  g_if4[(size_t)(FAN / 8) * NMID];            // cond idx packed u16

// ---------------------------------------------------------------------------
__device__ __forceinline__ void mma16816(float* d,
                                         uint32_t a0, uint32_t a1, uint32_t a2, uint32_t a3,
                                         uint32_t b0, uint32_t b1) {
    asm volatile(
        "mma.sync.aligned.m16n8k16.row.col.f32.bf16.bf16.f32 "
        "{%0,%1,%2,%3}, {%4,%5,%6,%7}, {%8,%9}, {%0,%1,%2,%3};"
        : "+f"(d[0]), "+f"(d[1]), "+f"(d[2]), "+f"(d[3])
        : "r"(a0), "r"(a1), "r"(a2), "r"(a3), "r"(b0), "r"(b1));
}

__device__ __forceinline__ void split_bf16(float v, __nv_bfloat16& h, __nv_bfloat16& l) {
    h = __float2bfloat16(v);
    l = __float2bfloat16(v - __bfloat162float(h));
}
// split float4 into packed hi (ushort4) and lo (ushort4)
__device__ __forceinline__ void split4(float4 v, ushort4& hv, ushort4& lv) {
    __nv_bfloat16 h0, h1, h2, h3, l0, l1, l2, l3;
    split_bf16(v.x, h0, l0); split_bf16(v.y, h1, l1);
    split_bf16(v.z, h2, l2); split_bf16(v.w, h3, l3);
    hv = make_ushort4(__bfloat16_as_ushort(h0), __bfloat16_as_ushort(h1),
                      __bfloat16_as_ushort(h2), __bfloat16_as_ushort(h3));
    lv = make_ushort4(__bfloat16_as_ushort(l0), __bfloat16_as_ushort(l1),
                      __bfloat16_as_ushort(l2), __bfloat16_as_ushort(l3));
}

// ---------------------------------------------------------------------------
// cond prep
// ---------------------------------------------------------------------------
__global__ void prep_w_kernel(const float* __restrict__ Wmid) {
    int t = blockIdx.x * blockDim.x + threadIdx.x;
    if (t >= NCOND * (FAN / 4) * NMID) return;
    int phase = t / ((FAN / 4) * NMID);
    int rem = t - phase * (FAN / 4) * NMID;
    int g = rem / NMID, o = rem - g * NMID;
    const float* src = Wmid + (size_t)(phase * NMID + o) * FAN + g * 4;
    g_wf4[phase][(size_t)g * NMID + o] = make_float4(src[0], src[1], src[2], src[3]);
}
__global__ void prep_i_kernel(const int* __restrict__ idx) {
    int t = blockIdx.x * blockDim.x + threadIdx.x;
    if (t >= (FAN / 8) * NMID) return;
    int g = t / NMID, o = t - g * NMID;
    const int* src = idx + (size_t)o * FAN + g * 8;
    uint4 v;
    v.x = (unsigned)(src[0] & (NMID - 1)) | ((unsigned)(src[1] & (NMID - 1)) << 16);
    v.y = (unsigned)(src[2] & (NMID - 1)) | ((unsigned)(src[3] & (NMID - 1)) << 16);
    v.z = (unsigned)(src[4] & (NMID - 1)) | ((unsigned)(src[5] & (NMID - 1)) << 16);
    v.w = (unsigned)(src[6] & (NMID - 1)) | ((unsigned)(src[7] & (NMID - 1)) << 16);
    g_if4[(size_t)g * NMID + o] = v;
}

// ---------------------------------------------------------------------------
// warp-MMA bf16-split GEMM, fp32 inputs converted during staging:
//   D[m][n] = sum_k A[m][k]*B[n][k], evaluated as Ah*Bh + Ah*Bl + Al*Bh
// MODE 0: A=Win(arg) B=x(arg),  Ks=NIN,  out: g_act0[m*B_SZ+n]=relu(D+bias[m])
// MODE 1: A=Wout(arg) B=g_a1t,  Ks=NMID, out: atomicAdd(out[n*NOUT+m], D); A rows >= NOUT -> 0
// ---------------------------------------------------------------------------
template <int MODE>
__global__ __launch_bounds__(GEMM_THREADS, 2) void mma_gemm(
    const float* __restrict__ Asrc, const float* __restrict__ Bsrc,
    const float* __restrict__ bias, float* __restrict__ outp, int kIters)
{
    const float* __restrict__ A = Asrc;
    const float* __restrict__ B = (MODE == 0) ? Bsrc : (const float*)g_a1t;
    float* out = (MODE == 0) ? (float*)g_act0v : outp;
    const int Ks = (MODE == 0) ? NIN : NMID;

    __shared__ __align__(16) char smAh[TBM * ROWB];
    __shared__ __align__(16) char smAl[TBM * ROWB];
    __shared__ __align__(16) char smBh[TBN * ROWB];
    __shared__ __align__(16) char smBl[TBN * ROWB];

    int tid = threadIdx.x;
    int wid = tid >> 5, lid = tid & 31;
    int g = lid >> 2, t = lid & 3;
    int wm = (wid >> 1) * 32;               // warp M offset in tile
    int wn = (wid & 1) * 64;                // warp N offset in tile
    int m0 = blockIdx.y * TBM;
    int n0 = blockIdx.x * TBN;
    int kk0 = blockIdx.z * kIters * TBK;

    // staging: tile = 128 rows x 32 fp32 (128B) = 1024 chunks of 16B; 4 per thread
    // chunk c: row = c>>3, seg = c&7 (4-float units)
    float4 fA[4], fB[4];
    float acc[2][8][4] = {};

#define LDG_CHUNKS(it)                                                              \
    do {                                                                            \
        int kk = kk0 + (it) * TBK;                                                  \
        _Pragma("unroll")                                                           \
        for (int q = 0; q < 4; q++) {                                               \
            int c = tid + q * GEMM_THREADS;                                         \
            int r = c >> 3, s = (c & 7) * 4;                                        \
            fA[q] = (MODE == 1 && m0 + r >= NOUT) ? make_float4(0.f, 0.f, 0.f, 0.f) \
                  : __ldg((const float4*)(A + (size_t)(m0 + r) * Ks + kk + s));     \
            fB[q] = __ldg((const float4*)(B + (size_t)(n0 + r) * Ks + kk + s));     \
        }                                                                           \
    } while (0)

#define CVT_STS()                                                                   \
    do {                                                                            \
        _Pragma("unroll")                                                           \
        for (int q = 0; q < 4; q++) {                                               \
            int c = tid + q * GEMM_THREADS;                                         \
            int r = c >> 3, sB = (c & 7) * 8;                                       \
            ushort4 hv, lv;                                                         \
            split4(fA[q], hv, lv);                                                  \
            *(ushort4*)(smAh + r * ROWB + sB) = hv;                                 \
            *(ushort4*)(smAl + r * ROWB + sB) = lv;                                 \
            split4(fB[q], hv, lv);                                                  \
            *(ushort4*)(smBh + r * ROWB + sB) = hv;                                 \
            *(ushort4*)(smBl + r * ROWB + sB) = lv;                                 \
        }                                                                           \
    } while (0)

    LDG_CHUNKS(0);

    for (int it = 0; it < kIters; it++) {
        __syncthreads();                    // previous compute done everywhere
        CVT_STS();
        __syncthreads();
        if (it + 1 < kIters) LDG_CHUNKS(it + 1);   // hidden under compute below

#pragma unroll
        for (int ks = 0; ks < 2; ks++) {
            int koff = ks * 32 + 4 * t;     // byte offset in 64B bf16 row
            uint32_t a[2][4];
            // ---- aH fragments (reused for Bh and Bl passes) ----
#pragma unroll
            for (int mi = 0; mi < 2; mi++) {
                const char* base = smAh + (wm + mi * 16 + g) * ROWB + koff;
                a[mi][0] = *(const uint32_t*)(base);
                a[mi][1] = *(const uint32_t*)(base + 8 * ROWB);
                a[mi][2] = *(const uint32_t*)(base + 16);
                a[mi][3] = *(const uint32_t*)(base + 8 * ROWB + 16);
            }
            // pass 0: aH x bH
#pragma unroll
            for (int nj = 0; nj < 4; nj++) {
                const char* bb = smBh + (wn + nj * 16 + g) * ROWB + koff;
                uint32_t b0 = *(const uint32_t*)(bb);
                uint32_t b1 = *(const uint32_t*)(bb + 16);
                uint32_t b2 = *(const uint32_t*)(bb + 8 * ROWB);
                uint32_t b3 = *(const uint32_t*)(bb + 8 * ROWB + 16);
#pragma unroll
                for (int mi = 0; mi < 2; mi++) {
                    mma16816(acc[mi][nj * 2],     a[mi][0], a[mi][1], a[mi][2], a[mi][3], b0, b1);
                    mma16816(acc[mi][nj * 2 + 1], a[mi][0], a[mi][1], a[mi][2], a[mi][3], b2, b3);
                }
            }
            // pass 1: aH x bL
#pragma unroll
            for (int nj = 0; nj < 4; nj++) {
                const char* bb = smBl + (wn + nj * 16 + g) * ROWB + koff;
                uint32_t b0 = *(const uint32_t*)(bb);
                uint32_t b1 = *(const uint32_t*)(bb + 16);
                uint32_t b2 = *(const uint32_t*)(bb + 8 * ROWB);
                uint32_t b3 = *(const uint32_t*)(bb + 8 * ROWB + 16);
#pragma unroll
                for (int mi = 0; mi < 2; mi++) {
                    mma16816(acc[mi][nj * 2],     a[mi][0], a[mi][1], a[mi][2], a[mi][3], b0, b1);
                    mma16816(acc[mi][nj * 2 + 1], a[mi][0], a[mi][1], a[mi][2], a[mi][3], b2, b3);
                }
            }
            // ---- aL fragments ----
#pragma unroll
            for (int mi = 0; mi < 2; mi++) {
                const char* base = smAl + (wm + mi * 16 + g) * ROWB + koff;
                a[mi][0] = *(const uint32_t*)(base);
                a[mi][1] = *(const uint32_t*)(base + 8 * ROWB);
                a[mi][2] = *(const uint32_t*)(base + 16);
                a[mi][3] = *(const uint32_t*)(base + 8 * ROWB + 16);
            }
            // pass 2: aL x bH
#pragma unroll
            for (int nj = 0; nj < 4; nj++) {
                const char* bb = smBh + (wn + nj * 16 + g) * ROWB + koff;
                uint32_t b0 = *(const uint32_t*)(bb);
                uint32_t b1 = *(const uint32_t*)(bb + 16);
                uint32_t b2 = *(const uint32_t*)(bb + 8 * ROWB);
                uint32_t b3 = *(const uint32_t*)(bb + 8 * ROWB + 16);
#pragma unroll
                for (int mi = 0; mi < 2; mi++) {
                    mma16816(acc[mi][nj * 2],     a[mi][0], a[mi][1], a[mi][2], a[mi][3], b0, b1);
                    mma16816(acc[mi][nj * 2 + 1], a[mi][0], a[mi][1], a[mi][2], a[mi][3], b2, b3);
                }
            }
        }
    }
#undef LDG_CHUNKS
#undef CVT_STS

    // epilogue: c0,c1 at (m, n=2t), c2,c3 at (m+8, n=2t)
    int mrow = g;
    int ncol = t * 2;
#pragma unroll
    for (int mi = 0; mi < 2; mi++) {
        int m = m0 + wm + mi * 16 + mrow;
        if (MODE == 0) {
            float bv0 = bias[m], bv8 = bias[m + 8];
#pragma unroll
            for (int n8 = 0; n8 < 8; n8++) {
                int n = n0 + wn + n8 * 8 + ncol;
                float* c = acc[mi][n8];
                float2 lo = make_float2(fmaxf(c[0] + bv0, 0.f), fmaxf(c[1] + bv0, 0.f));
                float2 hi = make_float2(fmaxf(c[2] + bv8, 0.f), fmaxf(c[3] + bv8, 0.f));
                *(float2*)(out + (size_t)m * B_SZ + n) = lo;
                *(float2*)(out + (size_t)(m + 8) * B_SZ + n) = hi;
            }
        } else {
#pragma unroll
            for (int n8 = 0; n8 < 8; n8++) {
                int n = n0 + wn + n8 * 8 + ncol;
                float* c = acc[mi][n8];
                if (m < NOUT) {
                    atomicAdd(out + (size_t)n * NOUT + m, c[0]);
                    atomicAdd(out + (size_t)(n + 1) * NOUT + m, c[1]);
                }
                if (m + 8 < NOUT) {
                    atomicAdd(out + (size_t)n * NOUT + m + 8, c[2]);
                    atomicAdd(out + (size_t)(n + 1) * NOUT + m + 8, c[3]);
                }
            }
        }
    }
}

// ---------------------------------------------------------------------------
// Condensed layer (R10-proven). phase 0: fp32 [o][b] -> fp32 [o][b]
//                               phase 1: fp32 [o][b] -> fp32 [b][o] (g_a1t)
// ---------------------------------------------------------------------------
__global__ __launch_bounds__(1024) void cond_kernel(int phase, const float* __restrict__ bias) {
    extern __shared__ float4 hs[];   // [NMID]
    const float4* hin = (phase == 0) ? g_act0v : g_act1v;
    const float4* wp = g_wf4[phase];
    int bq = blockIdx.x;
    int b0 = bq * 4;
    int tid = threadIdx.x;

    for (int j = tid; j < NMID; j += 1024)
        hs[j] = hin[(size_t)j * (B_SZ / 4) + bq];
    __syncthreads();

#pragma unroll
    for (int oi = 0; oi < NMID / 1024; oi++) {
        int o = oi * 1024 + tid;
        float ax = 0.f, ay = 0.f, az = 0.f, aw = 0.f;
#pragma unroll
        for (int g = 0; g < FAN / 8; g++) {
            uint4 iv = g_if4[(size_t)g * NMID + o];
            float4 w0 = wp[(size_t)(2 * g) * NMID + o];
            float4 w1 = wp[(size_t)(2 * g + 1) * NMID + o];
            float4 h0 = hs[iv.x & 0xffff];
            float4 h1 = hs[iv.x >> 16];
            float4 h2 = hs[iv.y & 0xffff];
            float4 h3 = hs[iv.y >> 16];
            float4 h4 = hs[iv.z & 0xffff];
            float4 h5 = hs[iv.z >> 16];
            float4 h6 = hs[iv.w & 0xffff];
            float4 h7 = hs[iv.w >> 16];
            ax = fmaf(w0.x, h0.x, ax); ay = fmaf(w0.x, h0.y, ay);
            az = fmaf(w0.x, h0.z, az); aw = fmaf(w0.x, h0.w, aw);
            ax = fmaf(w0.y, h1.x, ax); ay = fmaf(w0.y, h1.y, ay);
            az = fmaf(w0.y, h1.z, az); aw = fmaf(w0.y, h1.w, aw);
            ax = fmaf(w0.z, h2.x, ax); ay = fmaf(w0.z, h2.y, ay);
            az = fmaf(w0.z, h2.z, az); aw = fmaf(w0.z, h2.w, aw);
            ax = fmaf(w0.w, h3.x, ax); ay = fmaf(w0.w, h3.y, ay);
            az = fmaf(w0.w, h3.z, az); aw = fmaf(w0.w, h3.w, aw);
            ax = fmaf(w1.x, h4.x, ax); ay = fmaf(w1.x, h4.y, ay);
            az = fmaf(w1.x, h4.z, az); aw = fmaf(w1.x, h4.w, aw);
            ax = fmaf(w1.y, h5.x, ax); ay = fmaf(w1.y, h5.y, ay);
            az = fmaf(w1.y, h5.z, az); aw = fmaf(w1.y, h5.w, aw);
            ax = fmaf(w1.z, h6.x, ax); ay = fmaf(w1.z, h6.y, ay);
            az = fmaf(w1.z, h6.z, az); aw = fmaf(w1.z, h6.w, aw);
            ax = fmaf(w1.w, h7.x, ax); ay = fmaf(w1.w, h7.y, ay);
            az = fmaf(w1.w, h7.z, az); aw = fmaf(w1.w, h7.w, aw);
        }
        float bv = bias[o];
        float4 r;
        r.x = fmaxf(ax + bv, 0.f); r.y = fmaxf(ay + bv, 0.f);
        r.z = fmaxf(az + bv, 0.f); r.w = fmaxf(aw + bv, 0.f);
        if (phase == 0) {
            g_act1v[(size_t)o * (B_SZ / 4) + bq] = r;
        } else {
            g_a1t[(size_t)(b0 + 0) * NMID + o] = r.x;
            g_a1t[(size_t)(b0 + 1) * NMID + o] = r.y;
            g_a1t[(size_t)(b0 + 2) * NMID + o] = r.z;
            g_a1t[(size_t)(b0 + 3) * NMID + o] = r.w;
        }
    }
}

// ---------------------------------------------------------------------------
__global__ void init_out_kernel(const float* __restrict__ bout, float* __restrict__ out) {
    int t = blockIdx.x * blockDim.x + threadIdx.x;
    if (t < B_SZ * NOUT) out[t] = bout[t % NOUT];
}

// ---------------------------------------------------------------------------
extern "C" void kernel_launch(void* const* d_in, const int* in_sizes, int n_in,
                              void* d_out, int out_size) {
    const float* x    = (const float*)d_in[0];
    const float* Win  = (const float*)d_in[1];
    const float* bin  = (const float*)d_in[2];
    const float* Wmid = (const float*)d_in[3];
    const float* bmid = (const float*)d_in[4];
    const float* Wout = (const float*)d_in[5];
    const float* bout = (const float*)d_in[6];
    const int*   idx  = (const int*)d_in[7];    // int32 (JAX x64 disabled)
    float* out = (float*)d_out;

    cudaFuncSetAttribute(cond_kernel, cudaFuncAttributeMaxDynamicSharedMemorySize, 131072);

    // cond prep (scratch globals bound inside device code)
    prep_w_kernel<<<(NCOND * (FAN / 4) * NMID + 255) / 256, 256>>>(Wmid);
    prep_i_kernel<<<((FAN / 8) * NMID + 255) / 256, 256>>>(idx);

    // GEMM1: relu(W_in x^T + b_in) -> g_act0 fp32 [o][b]; fp32 staged, split in-kernel
    mma_gemm<0><<<dim3(B_SZ / TBN, NMID / TBM, 1), GEMM_THREADS>>>(
        Win, x, bin, nullptr, NIN / TBK);

    // condensed layers
    cond_kernel<<<B_SZ / 4, 1024, 131072>>>(0, bmid);
    cond_kernel<<<B_SZ / 4, 1024, 131072>>>(1, bmid + NMID);

    // GEMM3: out[b][m] = act1 . W_out^T + b_out  (split-K=8, atomic)
    init_out_kernel<<<(B_SZ * NOUT + 255) / 256, 256>>>(bout, out);
    mma_gemm<1><<<dim3(B_SZ / TBN, MPAD / TBM, 8), GEMM_THREADS>>>(
        Wout, nullptr, nullptr, out, NMID / (TBK * 8));
}